// round 8
// baseline (speedup 1.0000x reference)
#include <cuda_runtime.h>
#include <cuda_fp16.h>
#include <math.h>

#define Bc   4
#define C    48
#define C3   144
#define HH   256
#define WW   256
#define NPIX 65536   // HH*WW

typedef unsigned long long u64;

// packed f32x2 helpers (sm_100+: fma.rn.f32x2 = 2 fp32 FMAs / instruction)
__device__ __forceinline__ void ffma2(u64& d, u64 a, u64 b, u64 c) {
    asm("fma.rn.f32x2 %0, %1, %2, %3;" : "=l"(d) : "l"(a), "l"(b), "l"(c));
}
__device__ __forceinline__ u64 pack2(float x, float y) {
    u64 r; asm("mov.b64 %0, {%1, %2};" : "=l"(r) : "f"(x), "f"(y)); return r;
}
__device__ __forceinline__ void unpack2(float& x, float& y, u64 v) {
    asm("mov.b64 {%0, %1}, %2;" : "=f"(x), "=f"(y) : "l"(v));
}

// ---- scratch (device globals: no allocation allowed) ----
__device__ __half g_qkv[(size_t)Bc * C3 * NPIX];   // after 1x1 conv (75 MB)
__device__ __half g_dw [(size_t)Bc * C3 * NPIX];   // after depthwise (75 MB)
__device__ float  g_small[Bc * (C * C + 2 * C)];   // gram | qss | kss
__device__ float  g_M[Bc * C * C];                 // proj @ attn

// ============================================================
// K1: qkv 1x1 conv, GEMM W[144,48] x X[48,128px].
// 288 thr = 36 ocg(4 oc) x 8 pxg(16 px). x staged as NATIVE float4
// px-pairs (no dup, no convert); w duplicated into regs (4 pack2/k,
// amortized over 32 FFMA2). Per thread per k: 5 LDS.128 + 32 FFMA2.
// ============================================================
__global__ void __launch_bounds__(288) k_qkv(const float* __restrict__ x,
                                             const float* __restrict__ w) {
    __shared__ float Ws[24][C3];                   // k-major, 13.8 KB
    __shared__ __align__(16) u64 Xs[24][64];       // native px-pairs, 12.3 KB
    const int tid = threadIdx.x;
    const int b   = blockIdx.x >> 9;               // 512 tiles / batch
    const int px0 = (blockIdx.x & 511) << 7;       // 128 px / block
    const int pxg = tid & 7;                       // 8 groups x 16 px
    const int ocg = tid >> 3;                      // 36 groups x 4 oc
    const int oc0 = ocg * 4;
    const int xq  = pxg * 8;                       // u64 index

    const float* xb = x + (size_t)b * C * NPIX + px0;

    u64 acc[4][8];
#pragma unroll
    for (int o = 0; o < 4; o++)
#pragma unroll
        for (int j = 0; j < 8; j++) acc[o][j] = 0ull;

#pragma unroll 1
    for (int kc = 0; kc < C; kc += 24) {
        __syncthreads();
        for (int i = tid; i < 24 * C3; i += 288) {
            int kk = i / C3, oc = i % C3;
            Ws[kk][oc] = w[oc * C + kc + kk];
        }
        for (int i = tid; i < 24 * 32; i += 288) {
            int kk = i >> 5, q = i & 31;
            ((float4*)Xs[kk])[q] = *(const float4*)(xb + (size_t)(kc + kk) * NPIX + (q << 2));
        }
        __syncthreads();
#pragma unroll 4
        for (int kk = 0; kk < 24; kk++) {
            float4 wv = *(const float4*)&Ws[kk][oc0];
            u64 wd0 = pack2(wv.x, wv.x), wd1 = pack2(wv.y, wv.y);
            u64 wd2 = pack2(wv.z, wv.z), wd3 = pack2(wv.w, wv.w);
            u64 xv[8];
            *(uint4*)&xv[0] = *(const uint4*)&Xs[kk][xq];
            *(uint4*)&xv[2] = *(const uint4*)&Xs[kk][xq + 2];
            *(uint4*)&xv[4] = *(const uint4*)&Xs[kk][xq + 4];
            *(uint4*)&xv[6] = *(const uint4*)&Xs[kk][xq + 6];
#pragma unroll
            for (int j = 0; j < 8; j++) {
                ffma2(acc[0][j], wd0, xv[j], acc[0][j]);
                ffma2(acc[1][j], wd1, xv[j], acc[1][j]);
                ffma2(acc[2][j], wd2, xv[j], acc[2][j]);
                ffma2(acc[3][j], wd3, xv[j], acc[3][j]);
            }
        }
    }

    __half* ob = g_qkv + (size_t)b * C3 * NPIX + px0 + pxg * 16;
#pragma unroll
    for (int o = 0; o < 4; o++) {
        __half2 h[8];
#pragma unroll
        for (int j = 0; j < 8; j++) {
            float lo, hi; unpack2(lo, hi, acc[o][j]);
            h[j] = __floats2half2_rn(lo, hi);
        }
        __half* row = ob + (size_t)(oc0 + o) * NPIX;
        *(uint4*)row       = *(uint4*)&h[0];
        *(uint4*)(row + 8) = *(uint4*)&h[4];
    }
}

// ============================================================
// K2: depthwise 3x3, pad 1. Block = (b,ch,8-row tile), 256 threads.
// ============================================================
#define DWROWS 8
__global__ __launch_bounds__(256) void k_dw(const float* __restrict__ w) {
    const int tilesY = HH / DWROWS;
    const int ytile = blockIdx.x & (tilesY - 1);
    const int ch    = (blockIdx.x / tilesY) % C3;
    const int b     = blockIdx.x / (tilesY * C3);
    const int tid   = threadIdx.x;

    const __half* in  = g_qkv + ((size_t)b * C3 + ch) * NPIX;
    __half*       out = g_dw  + ((size_t)b * C3 + ch) * NPIX;

    __shared__ float rows[DWROWS + 2][WW];
    const int y0 = ytile * DWROWS;
    for (int i = tid; i < (DWROWS + 2) * (WW / 2); i += 256) {
        int r = i / (WW / 2), c2 = i % (WW / 2);
        int y = y0 - 1 + r;
        float2 v = make_float2(0.f, 0.f);
        if (y >= 0 && y < HH)
            v = __half22float2(*(const __half2*)(in + y * WW + 2 * c2));
        rows[r][2 * c2] = v.x; rows[r][2 * c2 + 1] = v.y;
    }
    __syncthreads();

    const float w00 = w[ch*9+0], w01 = w[ch*9+1], w02 = w[ch*9+2];
    const float w10 = w[ch*9+3], w11 = w[ch*9+4], w12 = w[ch*9+5];
    const float w20 = w[ch*9+6], w21 = w[ch*9+7], w22 = w[ch*9+8];

    const int half = tid >> 7;
    const int c2   = tid & 127;
    const int col0 = 2 * c2, col1 = col0 + 1;
    const float lm = (c2 > 0) ? 1.f : 0.f;
    const float rm = (c2 < 127) ? 1.f : 0.f;
    const int xl = max(col0 - 1, 0), xr = min(col1 + 1, WW - 1);

#pragma unroll
    for (int rr = 0; rr < DWROWS / 2; rr++) {
        const int r = 2 * rr + half;
        const float* r0 = rows[r], *r1 = rows[r + 1], *r2 = rows[r + 2];
        float a0 = r0[xl] * lm, b0 = r0[col0], c0v = r0[col1], d0 = r0[xr] * rm;
        float a1 = r1[xl] * lm, b1 = r1[col0], c1v = r1[col1], d1 = r1[xr] * rm;
        float a2 = r2[xl] * lm, b2 = r2[col0], c2v = r2[col1], d2 = r2[xr] * rm;
        float acc0 = w00*a0 + w01*b0 + w02*c0v + w10*a1 + w11*b1 + w12*c1v + w20*a2 + w21*b2 + w22*c2v;
        float acc1 = w00*b0 + w01*c0v + w02*d0 + w10*b1 + w11*c1v + w12*d1 + w20*b2 + w21*c2v + w22*d2;
        *(__half2*)(out + (y0 + r) * WW + col0) = __floats2half2_rn(acc0, acc1);
    }
}

// ============================================================
// K3: Gram G = Q K^T (48x48) + squared norms; FFMA2 over px pairs.
// ============================================================
#define TS2   32
#define CHUNK 1024
__global__ __launch_bounds__(256) void k_gram() {
    const int chunks = NPIX / CHUNK;
    const int b     = blockIdx.x / chunks;
    const int cbase = (blockIdx.x % chunks) * CHUNK;

    __shared__ float2 Qs[C][TS2 + 1], Ks[C][TS2 + 1];
    const int tid = threadIdx.x;
    const int c0 = (tid >> 4) * 3;
    const int d0 = (tid & 15) * 3;

    const __half* Q = g_dw + (size_t)b * C3 * NPIX;
    const __half* K = g_dw + (size_t)b * C3 * NPIX + (size_t)C * NPIX;

    u64 acc[3][3];
#pragma unroll
    for (int i = 0; i < 3; i++)
#pragma unroll
        for (int j = 0; j < 3; j++) acc[i][j] = 0ull;
    u64 sqa = 0ull;

    for (int sub = 0; sub < CHUNK / (2 * TS2); sub++) {
        const int tb = cbase + sub * (2 * TS2);
        for (int i = tid; i < C * TS2; i += 256) {
            int cc = i / TS2, t = i % TS2;
            Qs[cc][t] = __half22float2(*(const __half2*)(Q + (size_t)cc * NPIX + tb + 2 * t));
            Ks[cc][t] = __half22float2(*(const __half2*)(K + (size_t)cc * NPIX + tb + 2 * t));
        }
        __syncthreads();
#pragma unroll 4
        for (int t = 0; t < TS2; t++) {
            u64 q0 = *(const u64*)&Qs[c0][t];
            u64 q1 = *(const u64*)&Qs[c0 + 1][t];
            u64 q2 = *(const u64*)&Qs[c0 + 2][t];
            u64 k0 = *(const u64*)&Ks[d0][t];
            u64 k1 = *(const u64*)&Ks[d0 + 1][t];
            u64 k2 = *(const u64*)&Ks[d0 + 2][t];
            ffma2(acc[0][0], q0, k0, acc[0][0]); ffma2(acc[0][1], q0, k1, acc[0][1]); ffma2(acc[0][2], q0, k2, acc[0][2]);
            ffma2(acc[1][0], q1, k0, acc[1][0]); ffma2(acc[1][1], q1, k1, acc[1][1]); ffma2(acc[1][2], q1, k2, acc[1][2]);
            ffma2(acc[2][0], q2, k0, acc[2][0]); ffma2(acc[2][1], q2, k1, acc[2][1]); ffma2(acc[2][2], q2, k2, acc[2][2]);
            if (tid < C)          { u64 v = *(const u64*)&Qs[tid][t];     ffma2(sqa, v, v, sqa); }
            else if (tid < 2 * C) { u64 v = *(const u64*)&Ks[tid - C][t]; ffma2(sqa, v, v, sqa); }
        }
        __syncthreads();
    }

    float* gbase = g_small + b * (C * C + 2 * C);
#pragma unroll
    for (int i = 0; i < 3; i++)
#pragma unroll
        for (int j = 0; j < 3; j++) {
            float lo, hi; unpack2(lo, hi, acc[i][j]);
            atomicAdd(&gbase[(c0 + i) * C + (d0 + j)], lo + hi);
        }
    if (tid < 2 * C) { float lo, hi; unpack2(lo, hi, sqa); atomicAdd(&gbase[C * C + tid], lo + hi); }
}

// ============================================================
// K4: softmax(G/(qn*kn)*T) then M = proj @ attn -> g_M. 4 blocks.
// ============================================================
__global__ __launch_bounds__(256) void k_attn(const float* __restrict__ proj,
                                              const float* __restrict__ temp) {
    const int b = blockIdx.x;
    const int tid = threadIdx.x;
    const int warp = tid >> 5, lane = tid & 31;
    __shared__ float A[C][C + 1];
    __shared__ float P[C * C];
    __shared__ float qn[C], kn[C];
    const float* gbase = g_small + b * (C * C + 2 * C);
    const float T = temp[0];

    for (int i = tid; i < C * C; i += 256) P[i] = proj[i];
    if (tid < C)          qn[tid]     = fmaxf(sqrtf(gbase[C * C + tid]), 1e-12f);
    else if (tid < 2 * C) kn[tid - C] = fmaxf(sqrtf(gbase[C * C + tid]), 1e-12f);
    __syncthreads();

    for (int i = tid; i < C * C; i += 256) {
        int r = i / C, d = i % C;
        A[r][d] = gbase[i] * T / (qn[r] * kn[d]);
    }
    __syncthreads();

    for (int r = warp; r < C; r += 8) {
        float v0 = A[r][lane];
        float v1 = (lane + 32 < C) ? A[r][lane + 32] : -1e30f;
        float mx = fmaxf(v0, v1);
#pragma unroll
        for (int o = 16; o > 0; o >>= 1) mx = fmaxf(mx, __shfl_xor_sync(~0u, mx, o));
        float e0 = expf(v0 - mx);
        float e1 = (lane + 32 < C) ? expf(v1 - mx) : 0.f;
        float s = e0 + e1;
#pragma unroll
        for (int o = 16; o > 0; o >>= 1) s += __shfl_xor_sync(~0u, s, o);
        float inv = 1.f / s;
        A[r][lane] = e0 * inv;
        if (lane + 32 < C) A[r][lane + 32] = e1 * inv;
    }
    __syncthreads();

    // g_M[oc*C + d] = sum_c P[oc][c] * A[c][d]
    for (int i = tid; i < C * C; i += 256) {
        const int oc = i / C, d = i % C;
        float a = 0.f;
#pragma unroll
        for (int cc = 0; cc < C; cc++) a += P[oc * C + cc] * A[cc][d];
        g_M[b * C * C + i] = a;
    }
}

// ============================================================
// K5: out = M @ V, GEMM M[48,48] x V[48,256px].
// 192 thr = 12 ocg(4 oc) x 16 pxg(16 px). Same tile scheme as k_qkv.
// ============================================================
__global__ void __launch_bounds__(192) k_out(float* __restrict__ out) {
    __shared__ float Ms[24][C];                    // k-major M, 4.6 KB
    __shared__ __align__(16) u64 Xs[24][128];      // native px-pairs, 24.6 KB
    const int tid = threadIdx.x;
    const int b   = blockIdx.x >> 8;               // 256 tiles / batch
    const int px0 = (blockIdx.x & 255) << 8;       // 256 px / block
    const int pxg = tid & 15;                      // 16 groups x 16 px
    const int ocg = tid >> 4;                      // 12 groups x 4 oc
    const int oc0 = ocg * 4;
    const int xq  = pxg * 8;

    const __half* vb = g_dw + (size_t)b * C3 * NPIX + (size_t)(2 * C) * NPIX + px0;
    const float*  Mb = g_M + b * C * C;

    u64 acc[4][8];
#pragma unroll
    for (int o = 0; o < 4; o++)
#pragma unroll
        for (int j = 0; j < 8; j++) acc[o][j] = 0ull;

#pragma unroll 1
    for (int kc = 0; kc < C; kc += 24) {
        __syncthreads();
        for (int i = tid; i < 24 * C; i += 192) {
            int kk = i / C, oc = i % C;
            Ms[kk][oc] = Mb[oc * C + kc + kk];
        }
        // FIXED: 256 px per tile -> 64 quads per k row (was 32: half tile garbage)
        for (int i = tid; i < 24 * 64; i += 192) {
            int kk = i >> 6, q = i & 63;          // q: 4 px each
            uint2 raw = *(const uint2*)(vb + (size_t)(kc + kk) * NPIX + (q << 2));
            float2 f01 = __half22float2(*(__half2*)&raw.x);
            float2 f23 = __half22float2(*(__half2*)&raw.y);
            Xs[kk][q * 2]     = pack2(f01.x, f01.y);
            Xs[kk][q * 2 + 1] = pack2(f23.x, f23.y);
        }
        __syncthreads();
#pragma unroll 4
        for (int kk = 0; kk < 24; kk++) {
            float4 wv = *(const float4*)&Ms[kk][oc0];
            u64 wd0 = pack2(wv.x, wv.x), wd1 = pack2(wv.y, wv.y);
            u64 wd2 = pack2(wv.z, wv.z), wd3 = pack2(wv.w, wv.w);
            u64 xv[8];
            *(uint4*)&xv[0] = *(const uint4*)&Xs[kk][xq];
            *(uint4*)&xv[2] = *(const uint4*)&Xs[kk][xq + 2];
            *(uint4*)&xv[4] = *(const uint4*)&Xs[kk][xq + 4];
            *(uint4*)&xv[6] = *(const uint4*)&Xs[kk][xq + 6];
#pragma unroll
            for (int j = 0; j < 8; j++) {
                ffma2(acc[0][j], wd0, xv[j], acc[0][j]);
                ffma2(acc[1][j], wd1, xv[j], acc[1][j]);
                ffma2(acc[2][j], wd2, xv[j], acc[2][j]);
                ffma2(acc[3][j], wd3, xv[j], acc[3][j]);
            }
        }
    }

    float* ob = out + (size_t)b * C * NPIX + px0 + pxg * 16;
#pragma unroll
    for (int o = 0; o < 4; o++) {
        float* row = ob + (size_t)(oc0 + o) * NPIX;
        *(uint4*)(row)      = *(uint4*)&acc[o][0];
        *(uint4*)(row + 4)  = *(uint4*)&acc[o][2];
        *(uint4*)(row + 8)  = *(uint4*)&acc[o][4];
        *(uint4*)(row + 12) = *(uint4*)&acc[o][6];
    }
}

// ============================================================
extern "C" void kernel_launch(void* const* d_in, const int* in_sizes, int n_in,
                              void* d_out, int out_size) {
    const float* x      = (const float*)d_in[0];
    const float* qkv_w  = (const float*)d_in[1];
    const float* dw_w   = (const float*)d_in[2];
    const float* proj_w = (const float*)d_in[3];
    const float* temp   = (const float*)d_in[4];

    void* smallp = nullptr;
    cudaGetSymbolAddress(&smallp, g_small);
    cudaMemsetAsync(smallp, 0, sizeof(float) * Bc * (C * C + 2 * C));

    k_qkv <<<Bc * 512,                288>>>(x, qkv_w);
    k_dw  <<<Bc * C3 * (HH / DWROWS), 256>>>(dw_w);
    k_gram<<<Bc * (NPIX / CHUNK),     256>>>();
    k_attn<<<Bc,                      256>>>(proj_w, temp);
    k_out <<<Bc * 256,                192>>>((float*)d_out);
}

// round 9
// speedup vs baseline: 1.6463x; 1.6463x over previous
#include <cuda_runtime.h>
#include <cuda_fp16.h>
#include <math.h>

#define Bc   4
#define C    48
#define C3   144
#define HH   256
#define WW   256
#define NPIX 65536   // HH*WW

typedef unsigned long long u64;

__device__ __forceinline__ void ffma2(u64& d, u64 a, u64 b, u64 c) {
    asm("fma.rn.f32x2 %0, %1, %2, %3;" : "=l"(d) : "l"(a), "l"(b), "l"(c));
}
__device__ __forceinline__ u64 pack2(float x, float y) {
    u64 r; asm("mov.b64 %0, {%1, %2};" : "=l"(r) : "f"(x), "f"(y)); return r;
}
__device__ __forceinline__ void unpack2(float& x, float& y, u64 v) {
    asm("mov.b64 {%0, %1}, %2;" : "=f"(x), "=f"(y) : "l"(v));
}

// ---- scratch (device globals: no allocation allowed) ----
__device__ __half g_qkv[(size_t)Bc * C3 * NPIX];
__device__ __half g_dw [(size_t)Bc * C3 * NPIX];
__device__ float  g_small[Bc * (C * C + 2 * C)];
__device__ float  g_M[Bc * C * C];

// ============================================================
// K1: qkv 1x1 conv. acc packed over oc-pairs; w-pairs BROADCAST
// LDS.64 from smem; x one SEQUENTIAL LDS.128/k + 4 reg dups.
// 256 thr = 8 ocpg x 32 pxg; 9 pairs x 4 px per thread.
// W staged in two 24-k chunks (smem <= 38.4 KB).
// ============================================================
__global__ void __launch_bounds__(256) k_qkv(const float* __restrict__ x,
                                             const float* __restrict__ w) {
    __shared__ u64  Wp[24][72];                    // (w[2p][k],w[2p+1][k]), 13.8 KB
    __shared__ __align__(16) float Xs[C][128];     // x tile fp32, 24.6 KB
    const int tid  = threadIdx.x;
    const int b    = blockIdx.x >> 9;              // 512 tiles / batch
    const int px0  = (blockIdx.x & 511) << 7;      // 128 px / block
    const int pxg  = tid & 31;                     // warp-lane px group
    const int ocpg = tid >> 5;                     // warp-uniform: 0..7

    // stage X once (coalesced float4)
    const float* xb = x + (size_t)b * C * NPIX + px0;
    for (int i = tid; i < C * 32; i += 256) {
        int k = i >> 5, q = i & 31;
        *(float4*)&Xs[k][q * 4] = *(const float4*)(xb + (size_t)k * NPIX + (q << 2));
    }

    u64 acc[9][4];
#pragma unroll
    for (int j = 0; j < 9; j++)
#pragma unroll
        for (int q = 0; q < 4; q++) acc[j][q] = 0ull;

#pragma unroll 1
    for (int kc = 0; kc < C; kc += 24) {
        __syncthreads();
        for (int i = tid; i < 24 * 72; i += 256) {
            int kk = i / 72, p = i % 72;
            Wp[kk][p] = pack2(w[(2 * p) * C + kc + kk], w[(2 * p + 1) * C + kc + kk]);
        }
        __syncthreads();
#pragma unroll 4
        for (int kk = 0; kk < 24; kk++) {
            float4 xv = *(const float4*)&Xs[kc + kk][pxg * 4];
            u64 xd0 = pack2(xv.x, xv.x), xd1 = pack2(xv.y, xv.y);
            u64 xd2 = pack2(xv.z, xv.z), xd3 = pack2(xv.w, xv.w);
#pragma unroll
            for (int j = 0; j < 9; j++) {
                u64 wp = Wp[kk][ocpg * 9 + j];     // broadcast within warp
                ffma2(acc[j][0], wp, xd0, acc[j][0]);
                ffma2(acc[j][1], wp, xd1, acc[j][1]);
                ffma2(acc[j][2], wp, xd2, acc[j][2]);
                ffma2(acc[j][3], wp, xd3, acc[j][3]);
            }
        }
    }

    __half* ob = g_qkv + (size_t)b * C3 * NPIX + px0 + pxg * 4;
#pragma unroll
    for (int j = 0; j < 9; j++) {
        const int p = ocpg * 9 + j;
        float lo[4], hi[4];
#pragma unroll
        for (int q = 0; q < 4; q++) unpack2(lo[q], hi[q], acc[j][q]);
        uint2 slo, shi;
        *(__half2*)&slo.x = __floats2half2_rn(lo[0], lo[1]);
        *(__half2*)&slo.y = __floats2half2_rn(lo[2], lo[3]);
        *(__half2*)&shi.x = __floats2half2_rn(hi[0], hi[1]);
        *(__half2*)&shi.y = __floats2half2_rn(hi[2], hi[3]);
        *(uint2*)(ob + (size_t)(2 * p)     * NPIX) = slo;
        *(uint2*)(ob + (size_t)(2 * p + 1) * NPIX) = shi;
    }
}

// ============================================================
// K2: depthwise 3x3, pad 1 (unchanged from 344.6 baseline).
// ============================================================
#define DWROWS 8
__global__ __launch_bounds__(256) void k_dw(const float* __restrict__ w) {
    const int tilesY = HH / DWROWS;
    const int ytile = blockIdx.x & (tilesY - 1);
    const int ch    = (blockIdx.x / tilesY) % C3;
    const int b     = blockIdx.x / (tilesY * C3);
    const int tid   = threadIdx.x;

    const __half* in  = g_qkv + ((size_t)b * C3 + ch) * NPIX;
    __half*       out = g_dw  + ((size_t)b * C3 + ch) * NPIX;

    __shared__ float rows[DWROWS + 2][WW];
    const int y0 = ytile * DWROWS;
    for (int i = tid; i < (DWROWS + 2) * (WW / 2); i += 256) {
        int r = i / (WW / 2), c2 = i % (WW / 2);
        int y = y0 - 1 + r;
        float2 v = make_float2(0.f, 0.f);
        if (y >= 0 && y < HH)
            v = __half22float2(*(const __half2*)(in + y * WW + 2 * c2));
        rows[r][2 * c2] = v.x; rows[r][2 * c2 + 1] = v.y;
    }
    __syncthreads();

    const float w00 = w[ch*9+0], w01 = w[ch*9+1], w02 = w[ch*9+2];
    const float w10 = w[ch*9+3], w11 = w[ch*9+4], w12 = w[ch*9+5];
    const float w20 = w[ch*9+6], w21 = w[ch*9+7], w22 = w[ch*9+8];

    const int half = tid >> 7;
    const int c2   = tid & 127;
    const int col0 = 2 * c2, col1 = col0 + 1;
    const float lm = (c2 > 0) ? 1.f : 0.f;
    const float rm = (c2 < 127) ? 1.f : 0.f;
    const int xl = max(col0 - 1, 0), xr = min(col1 + 1, WW - 1);

#pragma unroll
    for (int rr = 0; rr < DWROWS / 2; rr++) {
        const int r = 2 * rr + half;
        const float* r0 = rows[r], *r1 = rows[r + 1], *r2 = rows[r + 2];
        float a0 = r0[xl] * lm, b0 = r0[col0], c0v = r0[col1], d0 = r0[xr] * rm;
        float a1 = r1[xl] * lm, b1 = r1[col0], c1v = r1[col1], d1 = r1[xr] * rm;
        float a2 = r2[xl] * lm, b2 = r2[col0], c2v = r2[col1], d2 = r2[xr] * rm;
        float acc0 = w00*a0 + w01*b0 + w02*c0v + w10*a1 + w11*b1 + w12*c1v + w20*a2 + w21*b2 + w22*c2v;
        float acc1 = w00*b0 + w01*c0v + w02*d0 + w10*b1 + w11*c1v + w12*d1 + w20*b2 + w21*c2v + w22*d2;
        *(__half2*)(out + (y0 + r) * WW + col0) = __floats2half2_rn(acc0, acc1);
    }
}

// ============================================================
// K3: Gram + norms (unchanged from 344.6 baseline).
// ============================================================
#define TS2   32
#define CHUNK 1024
__global__ __launch_bounds__(256) void k_gram() {
    const int chunks = NPIX / CHUNK;
    const int b     = blockIdx.x / chunks;
    const int cbase = (blockIdx.x % chunks) * CHUNK;

    __shared__ float2 Qs[C][TS2 + 1], Ks[C][TS2 + 1];
    const int tid = threadIdx.x;
    const int c0 = (tid >> 4) * 3;
    const int d0 = (tid & 15) * 3;

    const __half* Q = g_dw + (size_t)b * C3 * NPIX;
    const __half* K = g_dw + (size_t)b * C3 * NPIX + (size_t)C * NPIX;

    u64 acc[3][3];
#pragma unroll
    for (int i = 0; i < 3; i++)
#pragma unroll
        for (int j = 0; j < 3; j++) acc[i][j] = 0ull;
    u64 sqa = 0ull;

    for (int sub = 0; sub < CHUNK / (2 * TS2); sub++) {
        const int tb = cbase + sub * (2 * TS2);
        for (int i = tid; i < C * TS2; i += 256) {
            int cc = i / TS2, t = i % TS2;
            Qs[cc][t] = __half22float2(*(const __half2*)(Q + (size_t)cc * NPIX + tb + 2 * t));
            Ks[cc][t] = __half22float2(*(const __half2*)(K + (size_t)cc * NPIX + tb + 2 * t));
        }
        __syncthreads();
#pragma unroll 4
        for (int t = 0; t < TS2; t++) {
            u64 q0 = *(const u64*)&Qs[c0][t];
            u64 q1 = *(const u64*)&Qs[c0 + 1][t];
            u64 q2 = *(const u64*)&Qs[c0 + 2][t];
            u64 k0 = *(const u64*)&Ks[d0][t];
            u64 k1 = *(const u64*)&Ks[d0 + 1][t];
            u64 k2 = *(const u64*)&Ks[d0 + 2][t];
            ffma2(acc[0][0], q0, k0, acc[0][0]); ffma2(acc[0][1], q0, k1, acc[0][1]); ffma2(acc[0][2], q0, k2, acc[0][2]);
            ffma2(acc[1][0], q1, k0, acc[1][0]); ffma2(acc[1][1], q1, k1, acc[1][1]); ffma2(acc[1][2], q1, k2, acc[1][2]);
            ffma2(acc[2][0], q2, k0, acc[2][0]); ffma2(acc[2][1], q2, k1, acc[2][1]); ffma2(acc[2][2], q2, k2, acc[2][2]);
            if (tid < C)          { u64 v = *(const u64*)&Qs[tid][t];     ffma2(sqa, v, v, sqa); }
            else if (tid < 2 * C) { u64 v = *(const u64*)&Ks[tid - C][t]; ffma2(sqa, v, v, sqa); }
        }
        __syncthreads();
    }

    float* gbase = g_small + b * (C * C + 2 * C);
#pragma unroll
    for (int i = 0; i < 3; i++)
#pragma unroll
        for (int j = 0; j < 3; j++) {
            float lo, hi; unpack2(lo, hi, acc[i][j]);
            atomicAdd(&gbase[(c0 + i) * C + (d0 + j)], lo + hi);
        }
    if (tid < 2 * C) { float lo, hi; unpack2(lo, hi, sqa); atomicAdd(&gbase[C * C + tid], lo + hi); }
}

// ============================================================
// K4: softmax + M = proj @ attn (unchanged).
// ============================================================
__global__ __launch_bounds__(256) void k_attn(const float* __restrict__ proj,
                                              const float* __restrict__ temp) {
    const int b = blockIdx.x;
    const int tid = threadIdx.x;
    const int warp = tid >> 5, lane = tid & 31;
    __shared__ float A[C][C + 1];
    __shared__ float P[C * C];
    __shared__ float qn[C], kn[C];
    const float* gbase = g_small + b * (C * C + 2 * C);
    const float T = temp[0];

    for (int i = tid; i < C * C; i += 256) P[i] = proj[i];
    if (tid < C)          qn[tid]     = fmaxf(sqrtf(gbase[C * C + tid]), 1e-12f);
    else if (tid < 2 * C) kn[tid - C] = fmaxf(sqrtf(gbase[C * C + tid]), 1e-12f);
    __syncthreads();

    for (int i = tid; i < C * C; i += 256) {
        int r = i / C, d = i % C;
        A[r][d] = gbase[i] * T / (qn[r] * kn[d]);
    }
    __syncthreads();

    for (int r = warp; r < C; r += 8) {
        float v0 = A[r][lane];
        float v1 = (lane + 32 < C) ? A[r][lane + 32] : -1e30f;
        float mx = fmaxf(v0, v1);
#pragma unroll
        for (int o = 16; o > 0; o >>= 1) mx = fmaxf(mx, __shfl_xor_sync(~0u, mx, o));
        float e0 = expf(v0 - mx);
        float e1 = (lane + 32 < C) ? expf(v1 - mx) : 0.f;
        float s = e0 + e1;
#pragma unroll
        for (int o = 16; o > 0; o >>= 1) s += __shfl_xor_sync(~0u, s, o);
        float inv = 1.f / s;
        A[r][lane] = e0 * inv;
        if (lane + 32 < C) A[r][lane + 32] = e1 * inv;
    }
    __syncthreads();

    for (int i = tid; i < C * C; i += 256) {
        const int oc = i / C, d = i % C;
        float a = 0.f;
#pragma unroll
        for (int cc = 0; cc < C; cc++) a += P[oc * C + cc] * A[cc][d];
        g_M[b * C * C + i] = a;
    }
}

// ============================================================
// K5: out = M @ V. Same pairing scheme as K1.
// 128 thr = 4 ocpg x 32 pxg; 6 pairs x 4 px per thread.
// ============================================================
__global__ void __launch_bounds__(128) k_out(float* __restrict__ out) {
    __shared__ u64 Mp[C][24];                      // 9.2 KB
    __shared__ __align__(16) float Xs[C][128];     // 24.6 KB
    const int tid  = threadIdx.x;
    const int b    = blockIdx.x >> 9;              // 512 tiles / batch
    const int px0  = (blockIdx.x & 511) << 7;      // 128 px / block
    const int pxg  = tid & 31;
    const int ocpg = tid >> 5;                     // 0..3 (warp-uniform)

    const float* Mb = g_M + b * C * C;
    for (int i = tid; i < C * 24; i += 128) {
        int k = i / 24, p = i % 24;
        Mp[k][p] = pack2(Mb[(2 * p) * C + k], Mb[(2 * p + 1) * C + k]);
    }
    const __half* vb = g_dw + (size_t)b * C3 * NPIX + (size_t)(2 * C) * NPIX + px0;
    for (int i = tid; i < C * 32; i += 128) {
        int k = i >> 5, q = i & 31;
        uint2 raw = *(const uint2*)(vb + (size_t)k * NPIX + (q << 2));
        float2 f01 = __half22float2(*(__half2*)&raw.x);
        float2 f23 = __half22float2(*(__half2*)&raw.y);
        *(float4*)&Xs[k][q * 4] = make_float4(f01.x, f01.y, f23.x, f23.y);
    }
    __syncthreads();

    u64 acc[6][4];
#pragma unroll
    for (int j = 0; j < 6; j++)
#pragma unroll
        for (int q = 0; q < 4; q++) acc[j][q] = 0ull;

#pragma unroll 4
    for (int k = 0; k < C; k++) {
        float4 xv = *(const float4*)&Xs[k][pxg * 4];
        u64 xd0 = pack2(xv.x, xv.x), xd1 = pack2(xv.y, xv.y);
        u64 xd2 = pack2(xv.z, xv.z), xd3 = pack2(xv.w, xv.w);
#pragma unroll
        for (int j = 0; j < 6; j++) {
            u64 wp = Mp[k][ocpg * 6 + j];          // broadcast
            ffma2(acc[j][0], wp, xd0, acc[j][0]);
            ffma2(acc[j][1], wp, xd1, acc[j][1]);
            ffma2(acc[j][2], wp, xd2, acc[j][2]);
            ffma2(acc[j][3], wp, xd3, acc[j][3]);
        }
    }

    float* ob = out + (size_t)b * C * NPIX + px0 + pxg * 4;
#pragma unroll
    for (int j = 0; j < 6; j++) {
        const int p = ocpg * 6 + j;
        float lo[4], hi[4];
#pragma unroll
        for (int q = 0; q < 4; q++) unpack2(lo[q], hi[q], acc[j][q]);
        *(float4*)(ob + (size_t)(2 * p)     * NPIX) = make_float4(lo[0], lo[1], lo[2], lo[3]);
        *(float4*)(ob + (size_t)(2 * p + 1) * NPIX) = make_float4(hi[0], hi[1], hi[2], hi[3]);
    }
}

// ============================================================
extern "C" void kernel_launch(void* const* d_in, const int* in_sizes, int n_in,
                              void* d_out, int out_size) {
    const float* x      = (const float*)d_in[0];
    const float* qkv_w  = (const float*)d_in[1];
    const float* dw_w   = (const float*)d_in[2];
    const float* proj_w = (const float*)d_in[3];
    const float* temp   = (const float*)d_in[4];

    void* smallp = nullptr;
    cudaGetSymbolAddress(&smallp, g_small);
    cudaMemsetAsync(smallp, 0, sizeof(float) * Bc * (C * C + 2 * C));

    k_qkv <<<Bc * 512,                256>>>(x, qkv_w);
    k_dw  <<<Bc * C3 * (HH / DWROWS), 256>>>(dw_w);
    k_gram<<<Bc * (NPIX / CHUNK),     256>>>();
    k_attn<<<Bc,                      256>>>(proj_w, temp);
    k_out <<<Bc * 512,                128>>>((float*)d_out);
}

// round 11
// speedup vs baseline: 2.1375x; 1.2984x over previous
#include <cuda_runtime.h>
#include <cuda_fp16.h>
#include <stdint.h>
#include <math.h>

#define Bc   4
#define C    48
#define C3   144
#define HH   256
#define WW   256
#define NPIX 65536   // HH*WW

typedef unsigned long long u64;
typedef unsigned int u32;

__device__ __forceinline__ void ffma2(u64& d, u64 a, u64 b, u64 c) {
    asm("fma.rn.f32x2 %0, %1, %2, %3;" : "=l"(d) : "l"(a), "l"(b), "l"(c));
}
__device__ __forceinline__ u64 pack2(float x, float y) {
    u64 r; asm("mov.b64 %0, {%1, %2};" : "=l"(r) : "f"(x), "f"(y)); return r;
}
__device__ __forceinline__ void unpack2(float& x, float& y, u64 v) {
    asm("mov.b64 {%0, %1}, %2;" : "=f"(x), "=f"(y) : "l"(v));
}
__device__ __forceinline__ u32 smem_u32(const void* p) {
    return (u32)__cvta_generic_to_shared(p);
}

// ---- scratch (device globals: no allocation allowed) ----
__device__ __half g_qkv[(size_t)Bc * C3 * NPIX];
__device__ __half g_dw [(size_t)Bc * C3 * NPIX];
__device__ float  g_small[Bc * (C * C + 2 * C)];
__device__ float  g_M[Bc * C * C];

// ============================================================
// K1: qkv 1x1 conv via tensor cores (mma.m16n8k16 f16->f32).
// 288 thr = 9 warps = 9 m-tiles (144 oc). 128 px / block.
// A = W fp16 row-major (padded rows, conflict-free ldmatrix.x4);
// B = X fp16 [k][px] via ldmatrix.x2.trans.
// ============================================================
__global__ void __launch_bounds__(288) k_qkv(const float* __restrict__ x,
                                             const float* __restrict__ w) {
    __shared__ __half Ws[C3][56];    // 144 x (48+8 pad): row 112B = 7*16B
    __shared__ __half Xs[C][136];    // 48 x (128+8 pad): row 272B = 17*16B
    const int tid  = threadIdx.x;
    const int warp = tid >> 5, lane = tid & 31;
    const int b    = blockIdx.x >> 9;
    const int px0  = (blockIdx.x & 511) << 7;

    // stage W fp32 -> fp16 (row-major [oc][k])
    for (int i = tid; i < C3 * C; i += 288) {
        int m = i / C, k = i % C;
        Ws[m][k] = __float2half_rn(w[i]);
    }
    // stage X fp32 -> fp16, [k][px]
    const float* xb = x + (size_t)b * C * NPIX + px0;
    for (int i = tid; i < C * 32; i += 288) {
        int k = i >> 5, q = i & 31;
        float4 v = *(const float4*)(xb + (size_t)k * NPIX + (q << 2));
        *(__half2*)&Xs[k][q * 4]     = __floats2half2_rn(v.x, v.y);
        *(__half2*)&Xs[k][q * 4 + 2] = __floats2half2_rn(v.z, v.w);
    }
    __syncthreads();

    // A fragments for this warp's m-tile, all 3 k-steps (hoisted)
    const int m0 = warp * 16;
    u32 a[3][4];
#pragma unroll
    for (int ks = 0; ks < 3; ks++) {
        u32 addr = smem_u32(&Ws[m0 + (lane & 15)][(lane >> 4) * 8 + ks * 16]);
        asm volatile("ldmatrix.sync.aligned.m8n8.x4.shared.b16 {%0,%1,%2,%3}, [%4];"
                     : "=r"(a[ks][0]), "=r"(a[ks][1]), "=r"(a[ks][2]), "=r"(a[ks][3])
                     : "r"(addr));
    }

    __half* ob = g_qkv + (size_t)b * C3 * NPIX + px0;
    const int g = lane >> 2, t = lane & 3;
#pragma unroll 4
    for (int n = 0; n < 16; n++) {                 // 16 n-tiles of 8 px
        float c0 = 0.f, c1 = 0.f, c2 = 0.f, c3 = 0.f;
#pragma unroll
        for (int ks = 0; ks < 3; ks++) {
            u32 b0, b1;
            u32 baddr = smem_u32(&Xs[ks * 16 + (lane & 15)][n * 8]);
            asm volatile("ldmatrix.sync.aligned.m8n8.x2.trans.shared.b16 {%0,%1}, [%2];"
                         : "=r"(b0), "=r"(b1) : "r"(baddr));
            asm volatile("mma.sync.aligned.m16n8k16.row.col.f32.f16.f16.f32 "
                         "{%0,%1,%2,%3}, {%4,%5,%6,%7}, {%8,%9}, {%0,%1,%2,%3};"
                         : "+f"(c0), "+f"(c1), "+f"(c2), "+f"(c3)
                         : "r"(a[ks][0]), "r"(a[ks][1]), "r"(a[ks][2]), "r"(a[ks][3]),
                           "r"(b0), "r"(b1));
        }
        *(__half2*)(ob + (size_t)(m0 + g)     * NPIX + n * 8 + 2 * t) = __floats2half2_rn(c0, c1);
        *(__half2*)(ob + (size_t)(m0 + g + 8) * NPIX + n * 8 + 2 * t) = __floats2half2_rn(c2, c3);
    }
}

// ============================================================
// K2: depthwise 3x3, pad 1 (unchanged from 344.6 baseline).
// ============================================================
#define DWROWS 8
__global__ __launch_bounds__(256) void k_dw(const float* __restrict__ w) {
    const int tilesY = HH / DWROWS;
    const int ytile = blockIdx.x & (tilesY - 1);
    const int ch    = (blockIdx.x / tilesY) % C3;
    const int b     = blockIdx.x / (tilesY * C3);
    const int tid   = threadIdx.x;

    const __half* in  = g_qkv + ((size_t)b * C3 + ch) * NPIX;
    __half*       out = g_dw  + ((size_t)b * C3 + ch) * NPIX;

    __shared__ float rows[DWROWS + 2][WW];
    const int y0 = ytile * DWROWS;
    for (int i = tid; i < (DWROWS + 2) * (WW / 2); i += 256) {
        int r = i / (WW / 2), c2 = i % (WW / 2);
        int y = y0 - 1 + r;
        float2 v = make_float2(0.f, 0.f);
        if (y >= 0 && y < HH)
            v = __half22float2(*(const __half2*)(in + y * WW + 2 * c2));
        rows[r][2 * c2] = v.x; rows[r][2 * c2 + 1] = v.y;
    }
    __syncthreads();

    const float w00 = w[ch*9+0], w01 = w[ch*9+1], w02 = w[ch*9+2];
    const float w10 = w[ch*9+3], w11 = w[ch*9+4], w12 = w[ch*9+5];
    const float w20 = w[ch*9+6], w21 = w[ch*9+7], w22 = w[ch*9+8];

    const int half = tid >> 7;
    const int c2   = tid & 127;
    const int col0 = 2 * c2, col1 = col0 + 1;
    const float lm = (c2 > 0) ? 1.f : 0.f;
    const float rm = (c2 < 127) ? 1.f : 0.f;
    const int xl = max(col0 - 1, 0), xr = min(col1 + 1, WW - 1);

#pragma unroll
    for (int rr = 0; rr < DWROWS / 2; rr++) {
        const int r = 2 * rr + half;
        const float* r0 = rows[r], *r1 = rows[r + 1], *r2 = rows[r + 2];
        float a0 = r0[xl] * lm, b0 = r0[col0], c0v = r0[col1], d0 = r0[xr] * rm;
        float a1 = r1[xl] * lm, b1 = r1[col0], c1v = r1[col1], d1 = r1[xr] * rm;
        float a2 = r2[xl] * lm, b2 = r2[col0], c2v = r2[col1], d2 = r2[xr] * rm;
        float acc0 = w00*a0 + w01*b0 + w02*c0v + w10*a1 + w11*b1 + w12*c1v + w20*a2 + w21*b2 + w22*c2v;
        float acc1 = w00*b0 + w01*c0v + w02*d0 + w10*b1 + w11*c1v + w12*d1 + w20*b2 + w21*c2v + w22*d2;
        *(__half2*)(out + (y0 + r) * WW + col0) = __floats2half2_rn(acc0, acc1);
    }
}

// ============================================================
// K3: Gram + norms (unchanged).
// ============================================================
#define TS2   32
#define CHUNK 1024
__global__ __launch_bounds__(256) void k_gram() {
    const int chunks = NPIX / CHUNK;
    const int b     = blockIdx.x / chunks;
    const int cbase = (blockIdx.x % chunks) * CHUNK;

    __shared__ float2 Qs[C][TS2 + 1], Ks[C][TS2 + 1];
    const int tid = threadIdx.x;
    const int c0 = (tid >> 4) * 3;
    const int d0 = (tid & 15) * 3;

    const __half* Q = g_dw + (size_t)b * C3 * NPIX;
    const __half* K = g_dw + (size_t)b * C3 * NPIX + (size_t)C * NPIX;

    u64 acc[3][3];
#pragma unroll
    for (int i = 0; i < 3; i++)
#pragma unroll
        for (int j = 0; j < 3; j++) acc[i][j] = 0ull;
    u64 sqa = 0ull;

    for (int sub = 0; sub < CHUNK / (2 * TS2); sub++) {
        const int tb = cbase + sub * (2 * TS2);
        for (int i = tid; i < C * TS2; i += 256) {
            int cc = i / TS2, t = i % TS2;
            Qs[cc][t] = __half22float2(*(const __half2*)(Q + (size_t)cc * NPIX + tb + 2 * t));
            Ks[cc][t] = __half22float2(*(const __half2*)(K + (size_t)cc * NPIX + tb + 2 * t));
        }
        __syncthreads();
#pragma unroll 4
        for (int t = 0; t < TS2; t++) {
            u64 q0 = *(const u64*)&Qs[c0][t];
            u64 q1 = *(const u64*)&Qs[c0 + 1][t];
            u64 q2 = *(const u64*)&Qs[c0 + 2][t];
            u64 k0 = *(const u64*)&Ks[d0][t];
            u64 k1 = *(const u64*)&Ks[d0 + 1][t];
            u64 k2 = *(const u64*)&Ks[d0 + 2][t];
            ffma2(acc[0][0], q0, k0, acc[0][0]); ffma2(acc[0][1], q0, k1, acc[0][1]); ffma2(acc[0][2], q0, k2, acc[0][2]);
            ffma2(acc[1][0], q1, k0, acc[1][0]); ffma2(acc[1][1], q1, k1, acc[1][1]); ffma2(acc[1][2], q1, k2, acc[1][2]);
            ffma2(acc[2][0], q2, k0, acc[2][0]); ffma2(acc[2][1], q2, k1, acc[2][1]); ffma2(acc[2][2], q2, k2, acc[2][2]);
            if (tid < C)          { u64 v = *(const u64*)&Qs[tid][t];     ffma2(sqa, v, v, sqa); }
            else if (tid < 2 * C) { u64 v = *(const u64*)&Ks[tid - C][t]; ffma2(sqa, v, v, sqa); }
        }
        __syncthreads();
    }

    float* gbase = g_small + b * (C * C + 2 * C);
#pragma unroll
    for (int i = 0; i < 3; i++)
#pragma unroll
        for (int j = 0; j < 3; j++) {
            float lo, hi; unpack2(lo, hi, acc[i][j]);
            atomicAdd(&gbase[(c0 + i) * C + (d0 + j)], lo + hi);
        }
    if (tid < 2 * C) { float lo, hi; unpack2(lo, hi, sqa); atomicAdd(&gbase[C * C + tid], lo + hi); }
}

// ============================================================
// K4: softmax + M = proj @ attn. Warp-broadcast matmul loop.
// ============================================================
__global__ __launch_bounds__(256) void k_attn(const float* __restrict__ proj,
                                              const float* __restrict__ temp) {
    const int b = blockIdx.x;
    const int tid = threadIdx.x;
    const int warp = tid >> 5, lane = tid & 31;
    __shared__ float A[C][C + 1];
    __shared__ float P[C * C];
    __shared__ float qn[C], kn[C];
    const float* gbase = g_small + b * (C * C + 2 * C);
    const float T = temp[0];

    for (int i = tid; i < C * C; i += 256) P[i] = proj[i];
    if (tid < C)          qn[tid]     = fmaxf(sqrtf(gbase[C * C + tid]), 1e-12f);
    else if (tid < 2 * C) kn[tid - C] = fmaxf(sqrtf(gbase[C * C + tid]), 1e-12f);
    __syncthreads();

    for (int i = tid; i < C * C; i += 256) {
        int r = i / C, d = i % C;
        A[r][d] = gbase[i] * T / (qn[r] * kn[d]);
    }
    __syncthreads();

    for (int r = warp; r < C; r += 8) {
        float v0 = A[r][lane];
        float v1 = (lane + 32 < C) ? A[r][lane + 32] : -1e30f;
        float mx = fmaxf(v0, v1);
#pragma unroll
        for (int o = 16; o > 0; o >>= 1) mx = fmaxf(mx, __shfl_xor_sync(~0u, mx, o));
        float e0 = expf(v0 - mx);
        float e1 = (lane + 32 < C) ? expf(v1 - mx) : 0.f;
        float s = e0 + e1;
#pragma unroll
        for (int o = 16; o > 0; o >>= 1) s += __shfl_xor_sync(~0u, s, o);
        float inv = 1.f / s;
        A[r][lane] = e0 * inv;
        if (lane + 32 < C) A[r][lane + 32] = e1 * inv;
    }
    __syncthreads();

    // M = proj @ attn: warp per oc (broadcast P, sequential A)
    float* Mb = g_M + b * C * C;
    for (int oc = warp; oc < C; oc += 8) {
        float acc0 = 0.f, acc1 = 0.f;
#pragma unroll 8
        for (int cc = 0; cc < C; cc++) {
            float p = P[oc * C + cc];            // warp-uniform broadcast
            acc0 += p * A[cc][lane];
            acc1 += p * A[cc][(lane & 15) + 32];
        }
        Mb[oc * C + lane] = acc0;
        if (lane < 16) Mb[oc * C + 32 + lane] = acc1;
    }
}

// ============================================================
// K5: out = M @ V (R2-proven form: V in regs, M broadcast from smem).
// ============================================================
__global__ __launch_bounds__(256) void k_out(float* __restrict__ out) {
    __shared__ float Ms[C * C];
    const int tid = threadIdx.x;
    const int blocksPerBatch = NPIX / 512;
    const int b = blockIdx.x / blocksPerBatch;
    const int pbase = (blockIdx.x % blocksPerBatch) * 512 + tid * 2;

    for (int i = tid; i < C * C; i += 256) Ms[i] = g_M[b * C * C + i];
    __syncthreads();

    const __half* vb = g_dw + (size_t)b * C3 * NPIX + (size_t)(2 * C) * NPIX + pbase;
    float v0[C], v1[C];
#pragma unroll
    for (int cc = 0; cc < C; cc++) {
        float2 t = __half22float2(*(const __half2*)(vb + (size_t)cc * NPIX));
        v0[cc] = t.x; v1[cc] = t.y;
    }

    float* ob = out + (size_t)b * C * NPIX + pbase;
    for (int oc = 0; oc < C; oc++) {
        float a0 = 0.f, a1 = 0.f;
        const float4* mp = (const float4*)(Ms + oc * C);
#pragma unroll
        for (int i4 = 0; i4 < C / 4; i4++) {
            float4 m = mp[i4];
            a0 += m.x * v0[i4 * 4 + 0]; a1 += m.x * v1[i4 * 4 + 0];
            a0 += m.y * v0[i4 * 4 + 1]; a1 += m.y * v1[i4 * 4 + 1];
            a0 += m.z * v0[i4 * 4 + 2]; a1 += m.z * v1[i4 * 4 + 2];
            a0 += m.w * v0[i4 * 4 + 3]; a1 += m.w * v1[i4 * 4 + 3];
        }
        float2 o; o.x = a0; o.y = a1;
        *(float2*)(ob + (size_t)oc * NPIX) = o;
    }
}

// ============================================================
extern "C" void kernel_launch(void* const* d_in, const int* in_sizes, int n_in,
                              void* d_out, int out_size) {
    const float* x      = (const float*)d_in[0];
    const float* qkv_w  = (const float*)d_in[1];
    const float* dw_w   = (const float*)d_in[2];
    const float* proj_w = (const float*)d_in[3];
    const float* temp   = (const float*)d_in[4];

    void* smallp = nullptr;
    cudaGetSymbolAddress(&smallp, g_small);
    cudaMemsetAsync(smallp, 0, sizeof(float) * Bc * (C * C + 2 * C));

    k_qkv <<<Bc * 512,                288>>>(x, qkv_w);
    k_dw  <<<Bc * C3 * (HH / DWROWS), 256>>>(dw_w);
    k_gram<<<Bc * (NPIX / CHUNK),     256>>>();
    k_attn<<<Bc,                      256>>>(proj_w, temp);
    k_out <<<Bc * (NPIX / 512),       256>>>((float*)d_out);
}

// round 12
// speedup vs baseline: 3.2275x; 1.5100x over previous
#include <cuda_runtime.h>
#include <cuda_fp16.h>
#include <stdint.h>
#include <math.h>

#define Bc   4
#define C    48
#define C3   144
#define HH   256
#define WW   256
#define NPIX 65536   // HH*WW

typedef unsigned long long u64;
typedef unsigned int u32;

__device__ __forceinline__ u32 smem_u32(const void* p) {
    return (u32)__cvta_generic_to_shared(p);
}

// ---- scratch (device globals: no allocation allowed) ----
__device__ __half g_qkv[(size_t)Bc * C3 * NPIX];
__device__ __half g_dw [(size_t)Bc * C3 * NPIX];
__device__ float  g_small[Bc * (C * C + 2 * C)];
__device__ float  g_M[Bc * C * C];

// ============================================================
// K1: qkv 1x1 conv via mma.m16n8k16 (unchanged from R11 WIN).
// ============================================================
__global__ void __launch_bounds__(288) k_qkv(const float* __restrict__ x,
                                             const float* __restrict__ w) {
    __shared__ __half Ws[C3][56];    // rows 112B = 7*16B (conflict-free)
    __shared__ __half Xs[C][136];    // rows 272B = 17*16B
    const int tid  = threadIdx.x;
    const int warp = tid >> 5, lane = tid & 31;
    const int b    = blockIdx.x >> 9;
    const int px0  = (blockIdx.x & 511) << 7;

    for (int i = tid; i < C3 * C; i += 288) {
        int m = i / C, k = i % C;
        Ws[m][k] = __float2half_rn(w[i]);
    }
    const float* xb = x + (size_t)b * C * NPIX + px0;
    for (int i = tid; i < C * 32; i += 288) {
        int k = i >> 5, q = i & 31;
        float4 v = *(const float4*)(xb + (size_t)k * NPIX + (q << 2));
        *(__half2*)&Xs[k][q * 4]     = __floats2half2_rn(v.x, v.y);
        *(__half2*)&Xs[k][q * 4 + 2] = __floats2half2_rn(v.z, v.w);
    }
    __syncthreads();

    const int m0 = warp * 16;
    u32 a[3][4];
#pragma unroll
    for (int ks = 0; ks < 3; ks++) {
        u32 addr = smem_u32(&Ws[m0 + (lane & 15)][(lane >> 4) * 8 + ks * 16]);
        asm volatile("ldmatrix.sync.aligned.m8n8.x4.shared.b16 {%0,%1,%2,%3}, [%4];"
                     : "=r"(a[ks][0]), "=r"(a[ks][1]), "=r"(a[ks][2]), "=r"(a[ks][3])
                     : "r"(addr));
    }

    __half* ob = g_qkv + (size_t)b * C3 * NPIX + px0;
    const int g = lane >> 2, t = lane & 3;
#pragma unroll 4
    for (int n = 0; n < 16; n++) {
        float c0 = 0.f, c1 = 0.f, c2 = 0.f, c3 = 0.f;
#pragma unroll
        for (int ks = 0; ks < 3; ks++) {
            u32 b0, b1;
            u32 baddr = smem_u32(&Xs[ks * 16 + (lane & 15)][n * 8]);
            asm volatile("ldmatrix.sync.aligned.m8n8.x2.trans.shared.b16 {%0,%1}, [%2];"
                         : "=r"(b0), "=r"(b1) : "r"(baddr));
            asm volatile("mma.sync.aligned.m16n8k16.row.col.f32.f16.f16.f32 "
                         "{%0,%1,%2,%3}, {%4,%5,%6,%7}, {%8,%9}, {%0,%1,%2,%3};"
                         : "+f"(c0), "+f"(c1), "+f"(c2), "+f"(c3)
                         : "r"(a[ks][0]), "r"(a[ks][1]), "r"(a[ks][2]), "r"(a[ks][3]),
                           "r"(b0), "r"(b1));
        }
        *(__half2*)(ob + (size_t)(m0 + g)     * NPIX + n * 8 + 2 * t) = __floats2half2_rn(c0, c1);
        *(__half2*)(ob + (size_t)(m0 + g + 8) * NPIX + n * 8 + 2 * t) = __floats2half2_rn(c2, c3);
    }
}

// ============================================================
// K2: depthwise 3x3, pad 1 (unchanged).
// ============================================================
#define DWROWS 8
__global__ __launch_bounds__(256) void k_dw(const float* __restrict__ w) {
    const int tilesY = HH / DWROWS;
    const int ytile = blockIdx.x & (tilesY - 1);
    const int ch    = (blockIdx.x / tilesY) % C3;
    const int b     = blockIdx.x / (tilesY * C3);
    const int tid   = threadIdx.x;

    const __half* in  = g_qkv + ((size_t)b * C3 + ch) * NPIX;
    __half*       out = g_dw  + ((size_t)b * C3 + ch) * NPIX;

    __shared__ float rows[DWROWS + 2][WW];
    const int y0 = ytile * DWROWS;
    for (int i = tid; i < (DWROWS + 2) * (WW / 2); i += 256) {
        int r = i / (WW / 2), c2 = i % (WW / 2);
        int y = y0 - 1 + r;
        float2 v = make_float2(0.f, 0.f);
        if (y >= 0 && y < HH)
            v = __half22float2(*(const __half2*)(in + y * WW + 2 * c2));
        rows[r][2 * c2] = v.x; rows[r][2 * c2 + 1] = v.y;
    }
    __syncthreads();

    const float w00 = w[ch*9+0], w01 = w[ch*9+1], w02 = w[ch*9+2];
    const float w10 = w[ch*9+3], w11 = w[ch*9+4], w12 = w[ch*9+5];
    const float w20 = w[ch*9+6], w21 = w[ch*9+7], w22 = w[ch*9+8];

    const int half = tid >> 7;
    const int c2   = tid & 127;
    const int col0 = 2 * c2, col1 = col0 + 1;
    const float lm = (c2 > 0) ? 1.f : 0.f;
    const float rm = (c2 < 127) ? 1.f : 0.f;
    const int xl = max(col0 - 1, 0), xr = min(col1 + 1, WW - 1);

#pragma unroll
    for (int rr = 0; rr < DWROWS / 2; rr++) {
        const int r = 2 * rr + half;
        const float* r0 = rows[r], *r1 = rows[r + 1], *r2 = rows[r + 2];
        float a0 = r0[xl] * lm, b0 = r0[col0], c0v = r0[col1], d0 = r0[xr] * rm;
        float a1 = r1[xl] * lm, b1 = r1[col0], c1v = r1[col1], d1 = r1[xr] * rm;
        float a2 = r2[xl] * lm, b2 = r2[col0], c2v = r2[col1], d2 = r2[xr] * rm;
        float acc0 = w00*a0 + w01*b0 + w02*c0v + w10*a1 + w11*b1 + w12*c1v + w20*a2 + w21*b2 + w22*c2v;
        float acc1 = w00*b0 + w01*c0v + w02*d0 + w10*b1 + w11*c1v + w12*d1 + w20*b2 + w21*c2v + w22*d2;
        *(__half2*)(out + (y0 + r) * WW + col0) = __floats2half2_rn(acc0, acc1);
    }
}

// ============================================================
// K3: Gram via mma.m16n8k16. 192 thr = 6 warps.
// warp -> m-tile (warp>>1), n-range (warp&1)*24, 3 n-tiles each.
// A = Qs rows (same pattern as k_qkv A); B = Ks rows NON-trans
// (Ks[n][k] is transpose of k_qkv's B layout). Norms SIMT from smem.
// ============================================================
__global__ void __launch_bounds__(192) k_gram() {
    __shared__ __half Qs[C][136];
    __shared__ __half Ks[C][136];
    const int tid  = threadIdx.x;
    const int warp = tid >> 5, lane = tid & 31;
    const int b    = blockIdx.x >> 6;            // 64 blocks / batch
    const int px0  = (blockIdx.x & 63) << 10;    // 1024 px / block

    const __half* Q = g_dw + (size_t)b * C3 * NPIX;
    const __half* K = Q + (size_t)C * NPIX;

    const int m0     = (warp >> 1) * 16;
    const int n0base = (warp & 1) * 24;
    float c[3][4] = {{0.f}};
    float sq = 0.f;
    const int nch = tid % 96, npart = tid / 96;  // 96 ch x 2 halves

#pragma unroll 1
    for (int chk = 0; chk < 8; chk++) {
        const int tb = px0 + chk * 128;
        __syncthreads();
        for (int i = tid; i < C * 16; i += 192) {
            int k = i >> 4, q = i & 15;
            *(uint4*)&Qs[k][q * 8] = *(const uint4*)(Q + (size_t)k * NPIX + tb + q * 8);
            *(uint4*)&Ks[k][q * 8] = *(const uint4*)(K + (size_t)k * NPIX + tb + q * 8);
        }
        __syncthreads();

        // norms: thread sums 64 px of one channel
        {
            const __half2* r2 = (const __half2*)(((nch < C) ? Qs[nch] : Ks[nch - C]) + npart * 64);
#pragma unroll
            for (int j = 0; j < 32; j++) {
                float2 f = __half22float2(r2[j]);
                sq += f.x * f.x + f.y * f.y;
            }
        }

        // mma: 8 k-steps
#pragma unroll
        for (int ks = 0; ks < 8; ks++) {
            u32 a0r, a1r, a2r, a3r;
            u32 aaddr = smem_u32(&Qs[m0 + (lane & 15)][ks * 16 + (lane >> 4) * 8]);
            asm volatile("ldmatrix.sync.aligned.m8n8.x4.shared.b16 {%0,%1,%2,%3}, [%4];"
                         : "=r"(a0r), "=r"(a1r), "=r"(a2r), "=r"(a3r) : "r"(aaddr));
#pragma unroll
            for (int j = 0; j < 3; j++) {
                const int n0 = n0base + j * 8;
                u32 b0, b1;
                u32 baddr = smem_u32(&Ks[n0 + (lane & 7)][ks * 16 + ((lane >> 3) & 1) * 8]);
                asm volatile("ldmatrix.sync.aligned.m8n8.x2.shared.b16 {%0,%1}, [%2];"
                             : "=r"(b0), "=r"(b1) : "r"(baddr));
                asm volatile("mma.sync.aligned.m16n8k16.row.col.f32.f16.f16.f32 "
                             "{%0,%1,%2,%3}, {%4,%5,%6,%7}, {%8,%9}, {%0,%1,%2,%3};"
                             : "+f"(c[j][0]), "+f"(c[j][1]), "+f"(c[j][2]), "+f"(c[j][3])
                             : "r"(a0r), "r"(a1r), "r"(a2r), "r"(a3r), "r"(b0), "r"(b1));
            }
        }
    }

    float* gbase = g_small + b * (C * C + 2 * C);
    const int g = lane >> 2, t = lane & 3;
#pragma unroll
    for (int j = 0; j < 3; j++) {
        const int n0 = n0base + j * 8;
        atomicAdd(&gbase[(m0 + g)     * C + n0 + 2 * t],     c[j][0]);
        atomicAdd(&gbase[(m0 + g)     * C + n0 + 2 * t + 1], c[j][1]);
        atomicAdd(&gbase[(m0 + g + 8) * C + n0 + 2 * t],     c[j][2]);
        atomicAdd(&gbase[(m0 + g + 8) * C + n0 + 2 * t + 1], c[j][3]);
    }
    atomicAdd(&gbase[C * C + nch], sq);
}

// ============================================================
// K4: softmax + M = proj @ attn (unchanged).
// ============================================================
__global__ __launch_bounds__(256) void k_attn(const float* __restrict__ proj,
                                              const float* __restrict__ temp) {
    const int b = blockIdx.x;
    const int tid = threadIdx.x;
    const int warp = tid >> 5, lane = tid & 31;
    __shared__ float A[C][C + 1];
    __shared__ float P[C * C];
    __shared__ float qn[C], kn[C];
    const float* gbase = g_small + b * (C * C + 2 * C);
    const float T = temp[0];

    for (int i = tid; i < C * C; i += 256) P[i] = proj[i];
    if (tid < C)          qn[tid]     = fmaxf(sqrtf(gbase[C * C + tid]), 1e-12f);
    else if (tid < 2 * C) kn[tid - C] = fmaxf(sqrtf(gbase[C * C + tid]), 1e-12f);
    __syncthreads();

    for (int i = tid; i < C * C; i += 256) {
        int r = i / C, d = i % C;
        A[r][d] = gbase[i] * T / (qn[r] * kn[d]);
    }
    __syncthreads();

    for (int r = warp; r < C; r += 8) {
        float v0 = A[r][lane];
        float v1 = (lane + 32 < C) ? A[r][lane + 32] : -1e30f;
        float mx = fmaxf(v0, v1);
#pragma unroll
        for (int o = 16; o > 0; o >>= 1) mx = fmaxf(mx, __shfl_xor_sync(~0u, mx, o));
        float e0 = expf(v0 - mx);
        float e1 = (lane + 32 < C) ? expf(v1 - mx) : 0.f;
        float s = e0 + e1;
#pragma unroll
        for (int o = 16; o > 0; o >>= 1) s += __shfl_xor_sync(~0u, s, o);
        float inv = 1.f / s;
        A[r][lane] = e0 * inv;
        if (lane + 32 < C) A[r][lane + 32] = e1 * inv;
    }
    __syncthreads();

    float* Mb = g_M + b * C * C;
    for (int oc = warp; oc < C; oc += 8) {
        float acc0 = 0.f, acc1 = 0.f;
#pragma unroll 8
        for (int cc = 0; cc < C; cc++) {
            float p = P[oc * C + cc];
            acc0 += p * A[cc][lane];
            acc1 += p * A[cc][(lane & 15) + 32];
        }
        Mb[oc * C + lane] = acc0;
        if (lane < 16) Mb[oc * C + 32 + lane] = acc1;
    }
}

// ============================================================
// K5: out = M @ V via mma.m16n8k16 (k_qkv template, 3 m-tiles).
// 192 thr = 6 warps: m-tile = warp>>1, n-half = warp&1 (8 n-tiles).
// ============================================================
__global__ void __launch_bounds__(192) k_out(float* __restrict__ out) {
    __shared__ __half Ms[C][56];     // M fp16, rows 7*16B
    __shared__ __half Vs[C][136];    // V fp16, rows 17*16B
    const int tid  = threadIdx.x;
    const int warp = tid >> 5, lane = tid & 31;
    const int b    = blockIdx.x >> 9;
    const int px0  = (blockIdx.x & 511) << 7;

    const float* Mb = g_M + b * C * C;
    for (int i = tid; i < C * C; i += 192)
        Ms[i / C][i % C] = __float2half_rn(Mb[i]);
    const __half* vb = g_dw + (size_t)b * C3 * NPIX + (size_t)(2 * C) * NPIX + px0;
    for (int i = tid; i < C * 16; i += 192) {
        int k = i >> 4, q = i & 15;
        *(uint4*)&Vs[k][q * 8] = *(const uint4*)(vb + (size_t)k * NPIX + q * 8);
    }
    __syncthreads();

    const int m0 = (warp >> 1) * 16;
    u32 a[3][4];
#pragma unroll
    for (int ks = 0; ks < 3; ks++) {
        u32 addr = smem_u32(&Ms[m0 + (lane & 15)][ks * 16 + (lane >> 4) * 8]);
        asm volatile("ldmatrix.sync.aligned.m8n8.x4.shared.b16 {%0,%1,%2,%3}, [%4];"
                     : "=r"(a[ks][0]), "=r"(a[ks][1]), "=r"(a[ks][2]), "=r"(a[ks][3])
                     : "r"(addr));
    }

    float* ob = out + (size_t)b * C * NPIX + px0;
    const int g = lane >> 2, t = lane & 3;
#pragma unroll 4
    for (int j = 0; j < 8; j++) {
        const int n = (warp & 1) * 8 + j;
        float c0 = 0.f, c1 = 0.f, c2 = 0.f, c3 = 0.f;
#pragma unroll
        for (int ks = 0; ks < 3; ks++) {
            u32 b0, b1;
            u32 baddr = smem_u32(&Vs[ks * 16 + (lane & 15)][n * 8]);
            asm volatile("ldmatrix.sync.aligned.m8n8.x2.trans.shared.b16 {%0,%1}, [%2];"
                         : "=r"(b0), "=r"(b1) : "r"(baddr));
            asm volatile("mma.sync.aligned.m16n8k16.row.col.f32.f16.f16.f32 "
                         "{%0,%1,%2,%3}, {%4,%5,%6,%7}, {%8,%9}, {%0,%1,%2,%3};"
                         : "+f"(c0), "+f"(c1), "+f"(c2), "+f"(c3)
                         : "r"(a[ks][0]), "r"(a[ks][1]), "r"(a[ks][2]), "r"(a[ks][3]),
                           "r"(b0), "r"(b1));
        }
        *(float2*)(ob + (size_t)(m0 + g)     * NPIX + n * 8 + 2 * t) = make_float2(c0, c1);
        *(float2*)(ob + (size_t)(m0 + g + 8) * NPIX + n * 8 + 2 * t) = make_float2(c2, c3);
    }
}

// ============================================================
extern "C" void kernel_launch(void* const* d_in, const int* in_sizes, int n_in,
                              void* d_out, int out_size) {
    const float* x      = (const float*)d_in[0];
    const float* qkv_w  = (const float*)d_in[1];
    const float* dw_w   = (const float*)d_in[2];
    const float* proj_w = (const float*)d_in[3];
    const float* temp   = (const float*)d_in[4];

    void* smallp = nullptr;
    cudaGetSymbolAddress(&smallp, g_small);
    cudaMemsetAsync(smallp, 0, sizeof(float) * Bc * (C * C + 2 * C));

    k_qkv <<<Bc * 512,                288>>>(x, qkv_w);
    k_dw  <<<Bc * C3 * (HH / DWROWS), 256>>>(dw_w);
    k_gram<<<Bc * 64,                 192>>>();
    k_attn<<<Bc,                      256>>>(proj_w, temp);
    k_out <<<Bc * 512,                192>>>((float*)d_out);
}